// round 2
// baseline (speedup 1.0000x reference)
#include <cuda_runtime.h>

#define NTOK   4096
#define DMODEL 512
#define NH     8
#define DHD    64
#define WSZ    128
#define NP     32
#define DISP   64
#define QKV_LD 1536
#define MTOT   32768

// Scratch (device globals — allocation-free per harness rules)
__device__ float g_qkv[(size_t)MTOT * QKV_LD];   // [b*n_shifted, 3*H*DH]
__device__ float g_att[(size_t)MTOT * DMODEL];   // attention output, (patch window) order
__device__ float g_dummy_sink;

// ---------------------------------------------------------------------------
// Tiled fp32 GEMM: 128x128x16 tile, 256 threads, 8x8 micro (4+4 split).
// MODE 0: A = x with cyclic shift on row gather, B = Wqkv (ld 1536), C = g_qkv
// MODE 1: A = g_att, B = Wout (ld 512), C = out with +DISP roll scatter + bias
// ---------------------------------------------------------------------------
template<int MODE>
__global__ void __launch_bounds__(256)
gemm_kernel(const float* __restrict__ Ain, const float* __restrict__ Bm,
            const float* __restrict__ bias, float* __restrict__ Cout)
{
    constexpr int LDB = (MODE == 0) ? QKV_LD : DMODEL;
    const float* __restrict__ A = (MODE == 0) ? Ain : (const float*)g_att;
    float* __restrict__ C       = (MODE == 0) ? (float*)g_qkv : Cout;

    __shared__ float As[16][132];   // transposed A tile: As[k][m]
    __shared__ float Bs[16][128];

    const int tid = threadIdx.x;
    const int ty = tid >> 4, tx = tid & 15;
    const int m0 = blockIdx.y << 7;
    const int n0 = blockIdx.x << 7;

    // A load: each thread 2 rows x 1 float4
    const int ra = tid >> 2;            // 0..63 (and +64)
    const int kc = (tid & 3) << 2;      // 0,4,8,12
    // B load: each thread 2 rows x 1 float4
    const int kb = tid >> 5;            // 0..7 (and +8)
    const int nb = (tid & 31) << 2;     // 0..124

    const int gm0 = m0 + ra, gm1 = m0 + ra + 64;
    long arow0, arow1;
    if (MODE == 0) {
        const int b0r = gm0 >> 12, n0r = gm0 & 4095;
        const int b1r = gm1 >> 12, n1r = gm1 & 4095;
        arow0 = (long)((b0r << 12) | ((n0r + DISP) & 4095)) * DMODEL;
        arow1 = (long)((b1r << 12) | ((n1r + DISP) & 4095)) * DMODEL;
    } else {
        arow0 = (long)gm0 * DMODEL;
        arow1 = (long)gm1 * DMODEL;
    }

    float4 pa0 = *(const float4*)&A[arow0 + kc];
    float4 pa1 = *(const float4*)&A[arow1 + kc];
    float4 pb0 = *(const float4*)&Bm[(long)kb * LDB + n0 + nb];
    float4 pb1 = *(const float4*)&Bm[(long)(kb + 8) * LDB + n0 + nb];

    float acc[8][8];
#pragma unroll
    for (int r = 0; r < 8; r++)
#pragma unroll
        for (int c = 0; c < 8; c++) acc[r][c] = 0.f;

    for (int kt = 0; kt < DMODEL; kt += 16) {
        As[kc + 0][ra]      = pa0.x; As[kc + 1][ra]      = pa0.y;
        As[kc + 2][ra]      = pa0.z; As[kc + 3][ra]      = pa0.w;
        As[kc + 0][ra + 64] = pa1.x; As[kc + 1][ra + 64] = pa1.y;
        As[kc + 2][ra + 64] = pa1.z; As[kc + 3][ra + 64] = pa1.w;
        *(float4*)&Bs[kb][nb]     = pb0;
        *(float4*)&Bs[kb + 8][nb] = pb1;
        __syncthreads();

        if (kt + 16 < DMODEL) {   // register prefetch of next tile
            pa0 = *(const float4*)&A[arow0 + kt + 16 + kc];
            pa1 = *(const float4*)&A[arow1 + kt + 16 + kc];
            pb0 = *(const float4*)&Bm[(long)(kt + 16 + kb) * LDB + n0 + nb];
            pb1 = *(const float4*)&Bm[(long)(kt + 24 + kb) * LDB + n0 + nb];
        }

#pragma unroll
        for (int kk = 0; kk < 16; kk++) {
            float4 a0 = *(const float4*)&As[kk][ty << 2];
            float4 a1 = *(const float4*)&As[kk][64 + (ty << 2)];
            float4 b0 = *(const float4*)&Bs[kk][tx << 2];
            float4 b1 = *(const float4*)&Bs[kk][64 + (tx << 2)];
            float ar[8] = {a0.x, a0.y, a0.z, a0.w, a1.x, a1.y, a1.z, a1.w};
            float br[8] = {b0.x, b0.y, b0.z, b0.w, b1.x, b1.y, b1.z, b1.w};
#pragma unroll
            for (int r = 0; r < 8; r++)
#pragma unroll
                for (int c = 0; c < 8; c++)
                    acc[r][c] = fmaf(ar[r], br[c], acc[r][c]);
        }
        __syncthreads();
    }

    float4 bv0, bv1;
    if (MODE == 1) {
        bv0 = *(const float4*)&bias[n0 + (tx << 2)];
        bv1 = *(const float4*)&bias[n0 + 64 + (tx << 2)];
    }

#pragma unroll
    for (int r = 0; r < 8; r++) {
        const int mi = (r < 4) ? ((ty << 2) + r) : (64 + (ty << 2) + (r - 4));
        const int gm = m0 + mi;
        long crow;
        if (MODE == 1) {
            const int bb = gm >> 12, nn = gm & 4095;
            crow = (long)((bb << 12) | ((nn + DISP) & 4095)) * LDB;
        } else {
            crow = (long)gm * LDB;
        }
        float4 v0 = make_float4(acc[r][0], acc[r][1], acc[r][2], acc[r][3]);
        float4 v1 = make_float4(acc[r][4], acc[r][5], acc[r][6], acc[r][7]);
        if (MODE == 1) {
            v0.x += bv0.x; v0.y += bv0.y; v0.z += bv0.z; v0.w += bv0.w;
            v1.x += bv1.x; v1.y += bv1.y; v1.z += bv1.z; v1.w += bv1.w;
        }
        *(float4*)&C[crow + n0 + (tx << 2)]      = v0;
        *(float4*)&C[crow + n0 + 64 + (tx << 2)] = v1;
    }
}

// ---------------------------------------------------------------------------
// Windowed attention: one block per (b, h, window). 256 threads (16x16),
// 8x8 scores per thread, shfl softmax, P@V via smem-staged P.
// Input tokens of window pi:  n_in  = w*NP + pi   (w outer in input reshape)
// Output token of (pi, w):    n_out = pi*WSZ + w  (patch outer in output)
// ---------------------------------------------------------------------------
#define PADT 132
#define PADV 68
#define ATTN_SMEM_FLOATS (2 * 64 * PADT + 128 * PADV)   // 25600 floats = 100 KB

__global__ void __launch_bounds__(256)
attn_kernel(const float* __restrict__ pos_emb)
{
    extern __shared__ float sm[];
    float* Qt = sm;                 // [64][132]  (d-major, scaled by 1/8)
    float* Kt = sm + 64 * PADT;     // [64][132]
    float* Vs = sm + 2 * 64 * PADT; // [128][68]
    float* Ps = sm;                 // [128][132] overlays Qt+Kt (16896 floats)

    __shared__ float pe[2 * WSZ - 1];

    const int tid = threadIdx.x;
    const int ty = tid >> 4, tx = tid & 15;
    const int blk = blockIdx.x;
    const int pi = blk & 31;
    const int h  = (blk >> 5) & 7;
    const int b  = blk >> 8;

    for (int i = tid; i < 2 * WSZ - 1; i += 256) pe[i] = pos_emb[i];

    {   // load Q,K (transposed) and V; input tokens: n = w*NP + pi
        const int w    = tid >> 1;
        const int half = tid & 1;
        const long rbase = (long)((b << 12) + w * NP + pi) * QKV_LD + h * DHD;
#pragma unroll
        for (int j = 0; j < 8; j++) {
            const int d = (half << 5) + (j << 2);
            float4 q = *(const float4*)&g_qkv[rbase + d];
            float4 k = *(const float4*)&g_qkv[rbase + 512 + d];
            float4 v = *(const float4*)&g_qkv[rbase + 1024 + d];
            Qt[(d + 0) * PADT + w] = q.x * 0.125f;
            Qt[(d + 1) * PADT + w] = q.y * 0.125f;
            Qt[(d + 2) * PADT + w] = q.z * 0.125f;
            Qt[(d + 3) * PADT + w] = q.w * 0.125f;
            Kt[(d + 0) * PADT + w] = k.x;
            Kt[(d + 1) * PADT + w] = k.y;
            Kt[(d + 2) * PADT + w] = k.z;
            Kt[(d + 3) * PADT + w] = k.w;
            *(float4*)&Vs[w * PADV + d] = v;
        }
    }
    __syncthreads();

    int rowi[8];
#pragma unroll
    for (int r = 0; r < 8; r++)
        rowi[r] = (r < 4) ? ((ty << 2) + r) : (64 + (ty << 2) + (r - 4));

    float acc[8][8];
#pragma unroll
    for (int r = 0; r < 8; r++)
#pragma unroll
        for (int c = 0; c < 8; c++) acc[r][c] = 0.f;

    // scores = (Q*scale) @ K^T
#pragma unroll 8
    for (int d = 0; d < 64; d++) {
        float4 a0 = *(const float4*)&Qt[d * PADT + (ty << 2)];
        float4 a1 = *(const float4*)&Qt[d * PADT + 64 + (ty << 2)];
        float4 b0 = *(const float4*)&Kt[d * PADT + (tx << 2)];
        float4 b1 = *(const float4*)&Kt[d * PADT + 64 + (tx << 2)];
        float qr[8] = {a0.x, a0.y, a0.z, a0.w, a1.x, a1.y, a1.z, a1.w};
        float kr[8] = {b0.x, b0.y, b0.z, b0.w, b1.x, b1.y, b1.z, b1.w};
#pragma unroll
        for (int r = 0; r < 8; r++)
#pragma unroll
            for (int c = 0; c < 8; c++)
                acc[r][c] = fmaf(qr[r], kr[c], acc[r][c]);
    }

    // bias + shift mask + softmax (row spread over 16 tx lanes; shfl reduce)
#pragma unroll
    for (int r = 0; r < 8; r++) {
        const int i = rowi[r];
        float mx = -3.0e38f;
#pragma unroll
        for (int c = 0; c < 8; c++) {
            const int j = (c < 4) ? ((tx << 2) + c) : (64 + (tx << 2) + (c - 4));
            float s = acc[r][c] + pe[j - i + (WSZ - 1)];
            if ((r >= 4) != (c >= 4)) s -= 1e9f;   // quadrant shift mask
            acc[r][c] = s;
            mx = fmaxf(mx, s);
        }
#pragma unroll
        for (int o = 8; o > 0; o >>= 1)
            mx = fmaxf(mx, __shfl_xor_sync(0xffffffffu, mx, o));
        float sum = 0.f;
#pragma unroll
        for (int c = 0; c < 8; c++) {
            float e = __expf(acc[r][c] - mx);
            acc[r][c] = e;
            sum += e;
        }
#pragma unroll
        for (int o = 8; o > 0; o >>= 1)
            sum += __shfl_xor_sync(0xffffffffu, sum, o);
        const float inv = 1.0f / sum;
#pragma unroll
        for (int c = 0; c < 8; c++) acc[r][c] *= inv;
    }

    __syncthreads();   // Qt/Kt reads complete before P overlay write
#pragma unroll
    for (int r = 0; r < 8; r++) {
        *(float4*)&Ps[rowi[r] * PADT + (tx << 2)] =
            make_float4(acc[r][0], acc[r][1], acc[r][2], acc[r][3]);
        *(float4*)&Ps[rowi[r] * PADT + 64 + (tx << 2)] =
            make_float4(acc[r][4], acc[r][5], acc[r][6], acc[r][7]);
    }
    __syncthreads();

    // out = P @ V   (out tile 128x64; micro 8 rows x 4 cols)
    float o[8][4];
#pragma unroll
    for (int r = 0; r < 8; r++)
#pragma unroll
        for (int c = 0; c < 4; c++) o[r][c] = 0.f;

#pragma unroll 4
    for (int j = 0; j < WSZ; j++) {
        float4 v = *(const float4*)&Vs[j * PADV + (tx << 2)];
#pragma unroll
        for (int r = 0; r < 8; r++) {
            float p = Ps[rowi[r] * PADT + j];
            o[r][0] = fmaf(p, v.x, o[r][0]);
            o[r][1] = fmaf(p, v.y, o[r][1]);
            o[r][2] = fmaf(p, v.z, o[r][2]);
            o[r][3] = fmaf(p, v.w, o[r][3]);
        }
    }

    // OUTPUT rearrange: 'b head patch window dim -> b (patch window) (head dim)'
    // token_out = pi*WSZ + w   (NOT the inverse of the input windowing!)
#pragma unroll
    for (int r = 0; r < 8; r++) {
        const long orow = (long)((b << 12) + pi * WSZ + rowi[r]) * DMODEL
                        + h * DHD + (tx << 2);
        *(float4*)&g_att[orow] = make_float4(o[r][0], o[r][1], o[r][2], o[r][3]);
    }
}

// ---------------------------------------------------------------------------
extern "C" void kernel_launch(void* const* d_in, const int* in_sizes, int n_in,
                              void* d_out, int out_size)
{
    const float* x       = (const float*)d_in[0];
    const float* Wqkv    = (const float*)d_in[1];
    const float* pos_emb = (const float*)d_in[2];
    const float* Wout    = (const float*)d_in[3];
    const float* bout    = (const float*)d_in[4];
    float* out = (float*)d_out;

    cudaFuncSetAttribute(attn_kernel, cudaFuncAttributeMaxDynamicSharedMemorySize,
                         (int)(ATTN_SMEM_FLOATS * sizeof(float)));

    // 1) qkv = roll(x,-64) @ Wqkv
    gemm_kernel<0><<<dim3(12, 256), 256>>>(x, Wqkv, nullptr, nullptr);
    // 2) windowed attention (2048 windows)
    attn_kernel<<<2048, 256, ATTN_SMEM_FLOATS * sizeof(float)>>>(pos_emb);
    // 3) out = attn @ Wout + bout, rolled back by +64
    gemm_kernel<1><<<dim3(4, 256), 256>>>(nullptr, Wout, bout, out);
}

// round 3
// speedup vs baseline: 1.1926x; 1.1926x over previous
#include <cuda_runtime.h>

#define NTOK   4096
#define DMODEL 512
#define NH     8
#define DHD    64
#define WSZ    128
#define NP     32
#define DISP   64
#define QKV_LD 1536
#define MTOT   32768

// Scratch (device globals — allocation-free per harness rules)
__device__ float g_qkv[(size_t)MTOT * QKV_LD];   // [b*n_shifted, 3*H*DH]
__device__ float g_att[(size_t)MTOT * DMODEL];   // attention output, (patch window) order

// ---------------------------------------------------------------------------
// helpers
// ---------------------------------------------------------------------------
__device__ __forceinline__ unsigned smem_u32(const void* p) {
    return (unsigned)__cvta_generic_to_shared(p);
}
__device__ __forceinline__ unsigned f2tf(float x) {
    unsigned r;
    asm("cvt.rna.tf32.f32 %0, %1;" : "=r"(r) : "f"(x));
    return r;
}
__device__ __forceinline__ void mma_tf32(float* d, const unsigned* a, const unsigned* b) {
    asm volatile(
        "mma.sync.aligned.m16n8k8.row.col.f32.tf32.tf32.f32 "
        "{%0,%1,%2,%3}, {%4,%5,%6,%7}, {%8,%9}, {%0,%1,%2,%3};\n"
        : "+f"(d[0]), "+f"(d[1]), "+f"(d[2]), "+f"(d[3])
        : "r"(a[0]), "r"(a[1]), "r"(a[2]), "r"(a[3]), "r"(b[0]), "r"(b[1]));
}
#define CP16(dst, src) \
    asm volatile("cp.async.ca.shared.global [%0], [%1], 16;\n" :: "r"(dst), "l"(src))

// ---------------------------------------------------------------------------
// 3xTF32 tensor-core GEMM: 128x128x16 tile, 256 thr, warp grid 2(M)x4(N),
// warp tile 64x32 (4x4 m16n8k8 tiles), cp.async 2-stage pipeline.
// MODE 0: A = x with cyclic shift row gather, B = Wqkv (ld 1536), C = g_qkv
// MODE 1: A = g_att, B = Wout (ld 512), C = out with +DISP roll scatter + bias
// ---------------------------------------------------------------------------
#define BM 128
#define BN 128
#define BK 16
#define APAD 20
#define BPAD 136
#define NKIT (DMODEL / BK)   // 32

template<int MODE>
__global__ void __launch_bounds__(256)
gemm_tf32(const float* __restrict__ Ain, const float* __restrict__ Bm,
          const float* __restrict__ bias, float* __restrict__ Cout)
{
    constexpr int LDB = (MODE == 0) ? QKV_LD : DMODEL;
    const float* __restrict__ A = (MODE == 0) ? Ain : (const float*)g_att;
    float* __restrict__ C       = (MODE == 0) ? (float*)g_qkv : Cout;

    __shared__ __align__(16) float As[2][BM * APAD];
    __shared__ __align__(16) float Bs[2][BK * BPAD];

    const int tid  = threadIdx.x;
    const int lane = tid & 31;
    const int wid  = tid >> 5;
    const int g    = lane >> 2;      // 0..7
    const int c    = lane & 3;       // 0..3
    const int wm   = (wid >> 2) * 64;  // warp M offset: 0 / 64
    const int wn   = (wid & 3) * 32;   // warp N offset: 0..96

    const int m0 = blockIdx.y << 7;
    const int n0 = blockIdx.x << 7;

    // --- gmem load assignments ---
    const int ar = tid >> 1;              // A row in tile, 0..127
    const int ac = (tid & 1) * 8;         // 0 or 8
    const int gm = m0 + ar;
    long arow;
    if (MODE == 0) {
        const int bb = gm >> 12, nn = gm & 4095;
        arow = (long)((bb << 12) | ((nn + DISP) & 4095)) * DMODEL;
    } else {
        arow = (long)gm * DMODEL;
    }
    const float* aptr = A + arow + ac;

    const int brw = tid >> 4;             // B k-row in tile, 0..15
    const int bc  = (tid & 15) * 8;       // 0..120
    const float* bptr = Bm + (long)brw * LDB + n0 + bc;

    const unsigned asd = smem_u32(&As[0][ar * APAD + ac]);
    const unsigned bsd = smem_u32(&Bs[0][brw * BPAD + bc]);
    const unsigned stA = sizeof(float) * BM * APAD;
    const unsigned stB = sizeof(float) * BK * BPAD;

    float acc[4][4][4];
#pragma unroll
    for (int mt = 0; mt < 4; mt++)
#pragma unroll
        for (int nt = 0; nt < 4; nt++)
#pragma unroll
            for (int i = 0; i < 4; i++) acc[mt][nt][i] = 0.f;

    // prefetch stage 0
    {
        CP16(asd, aptr);  CP16(asd + 16, aptr + 4);
        CP16(bsd, bptr);  CP16(bsd + 16, bptr + 4);
        asm volatile("cp.async.commit_group;\n");
    }

#pragma unroll 1
    for (int kt = 0; kt < NKIT; kt++) {
        const int s = kt & 1;
        if (kt + 1 < NKIT) {
            const int s2 = (kt + 1) & 1;
            const float* ap = aptr + (kt + 1) * BK;
            const float* bp = bptr + (long)(kt + 1) * BK * LDB;
            CP16(asd + s2 * stA, ap);  CP16(asd + s2 * stA + 16, ap + 4);
            CP16(bsd + s2 * stB, bp);  CP16(bsd + s2 * stB + 16, bp + 4);
            asm volatile("cp.async.commit_group;\n");
            asm volatile("cp.async.wait_group 1;\n");
        } else {
            asm volatile("cp.async.wait_group 0;\n");
        }
        __syncthreads();

        const float* as = As[s];
        const float* bs = Bs[s];
#pragma unroll
        for (int ks = 0; ks < 2; ks++) {
            const int k0 = ks * 8;
            unsigned ahi[4][4], alo[4][4];
#pragma unroll
            for (int mt = 0; mt < 4; mt++) {
                const int mb = wm + mt * 16 + g;
#pragma unroll
                for (int i = 0; i < 4; i++) {
                    const int row = mb + (i & 1) * 8;
                    const int col = k0 + c + (i >> 1) * 4;
                    const float v = as[row * APAD + col];
                    const unsigned h = f2tf(v);
                    ahi[mt][i] = h;
                    alo[mt][i] = f2tf(v - __uint_as_float(h));
                }
            }
            unsigned bhi[4][2], blo[4][2];
#pragma unroll
            for (int nt = 0; nt < 4; nt++) {
#pragma unroll
                for (int j = 0; j < 2; j++) {
                    const float v = bs[(k0 + c + j * 4) * BPAD + wn + nt * 8 + g];
                    const unsigned h = f2tf(v);
                    bhi[nt][j] = h;
                    blo[nt][j] = f2tf(v - __uint_as_float(h));
                }
            }
#pragma unroll
            for (int mt = 0; mt < 4; mt++)
#pragma unroll
                for (int nt = 0; nt < 4; nt++) {
                    mma_tf32(acc[mt][nt], alo[mt], bhi[nt]);
                    mma_tf32(acc[mt][nt], ahi[mt], blo[nt]);
                    mma_tf32(acc[mt][nt], ahi[mt], bhi[nt]);
                }
        }
        __syncthreads();
    }

    // epilogue
    float2 bv[4];
    if (MODE == 1) {
#pragma unroll
        for (int nt = 0; nt < 4; nt++)
            bv[nt] = *(const float2*)&bias[n0 + wn + nt * 8 + 2 * c];
    }

#pragma unroll
    for (int mt = 0; mt < 4; mt++) {
#pragma unroll
        for (int half = 0; half < 2; half++) {
            const int row = m0 + wm + mt * 16 + g + half * 8;
            long crow;
            if (MODE == 1) {
                const int bb = row >> 12, nn = row & 4095;
                crow = (long)((bb << 12) | ((nn + DISP) & 4095)) * LDB;
            } else {
                crow = (long)row * LDB;
            }
#pragma unroll
            for (int nt = 0; nt < 4; nt++) {
                float x = acc[mt][nt][half * 2 + 0];
                float y = acc[mt][nt][half * 2 + 1];
                if (MODE == 1) { x += bv[nt].x; y += bv[nt].y; }
                *(float2*)&C[crow + n0 + wn + nt * 8 + 2 * c] = make_float2(x, y);
            }
        }
    }
}

// ---------------------------------------------------------------------------
// Windowed attention: one block per (b, h, window). 256 threads (16x16),
// 8x8 scores per thread, shfl softmax, P@V via smem-staged P.
// Input tokens of window pi:  n_in  = w*NP + pi   (w outer in input reshape)
// Output token of (pi, w):    n_out = pi*WSZ + w  (patch outer in output)
// ---------------------------------------------------------------------------
#define PADT 132
#define PADV 68
#define ATTN_SMEM_FLOATS (2 * 64 * PADT + 128 * PADV)   // 25600 floats = 100 KB

__global__ void __launch_bounds__(256)
attn_kernel(const float* __restrict__ pos_emb)
{
    extern __shared__ float sm[];
    float* Qt = sm;                 // [64][132]  (d-major, scaled by 1/8)
    float* Kt = sm + 64 * PADT;     // [64][132]
    float* Vs = sm + 2 * 64 * PADT; // [128][68]
    float* Ps = sm;                 // [128][132] overlays Qt+Kt

    __shared__ float pe[2 * WSZ - 1];

    const int tid = threadIdx.x;
    const int ty = tid >> 4, tx = tid & 15;
    const int blk = blockIdx.x;
    const int pi = blk & 31;
    const int h  = (blk >> 5) & 7;
    const int b  = blk >> 8;

    for (int i = tid; i < 2 * WSZ - 1; i += 256) pe[i] = pos_emb[i];

    {   // load Q,K (transposed) and V; input tokens: n = w*NP + pi
        const int w    = tid >> 1;
        const int half = tid & 1;
        const long rbase = (long)((b << 12) + w * NP + pi) * QKV_LD + h * DHD;
#pragma unroll
        for (int j = 0; j < 8; j++) {
            const int d = (half << 5) + (j << 2);
            float4 q = *(const float4*)&g_qkv[rbase + d];
            float4 k = *(const float4*)&g_qkv[rbase + 512 + d];
            float4 v = *(const float4*)&g_qkv[rbase + 1024 + d];
            Qt[(d + 0) * PADT + w] = q.x * 0.125f;
            Qt[(d + 1) * PADT + w] = q.y * 0.125f;
            Qt[(d + 2) * PADT + w] = q.z * 0.125f;
            Qt[(d + 3) * PADT + w] = q.w * 0.125f;
            Kt[(d + 0) * PADT + w] = k.x;
            Kt[(d + 1) * PADT + w] = k.y;
            Kt[(d + 2) * PADT + w] = k.z;
            Kt[(d + 3) * PADT + w] = k.w;
            *(float4*)&Vs[w * PADV + d] = v;
        }
    }
    __syncthreads();

    int rowi[8];
#pragma unroll
    for (int r = 0; r < 8; r++)
        rowi[r] = (r < 4) ? ((ty << 2) + r) : (64 + (ty << 2) + (r - 4));

    float acc[8][8];
#pragma unroll
    for (int r = 0; r < 8; r++)
#pragma unroll
        for (int c = 0; c < 8; c++) acc[r][c] = 0.f;

    // scores = (Q*scale) @ K^T
#pragma unroll 8
    for (int d = 0; d < 64; d++) {
        float4 a0 = *(const float4*)&Qt[d * PADT + (ty << 2)];
        float4 a1 = *(const float4*)&Qt[d * PADT + 64 + (ty << 2)];
        float4 b0 = *(const float4*)&Kt[d * PADT + (tx << 2)];
        float4 b1 = *(const float4*)&Kt[d * PADT + 64 + (tx << 2)];
        float qr[8] = {a0.x, a0.y, a0.z, a0.w, a1.x, a1.y, a1.z, a1.w};
        float kr[8] = {b0.x, b0.y, b0.z, b0.w, b1.x, b1.y, b1.z, b1.w};
#pragma unroll
        for (int r = 0; r < 8; r++)
#pragma unroll
            for (int c = 0; c < 8; c++)
                acc[r][c] = fmaf(qr[r], kr[c], acc[r][c]);
    }

    // bias + shift mask + softmax (row spread over 16 tx lanes; shfl reduce)
#pragma unroll
    for (int r = 0; r < 8; r++) {
        const int i = rowi[r];
        float mx = -3.0e38f;
#pragma unroll
        for (int c = 0; c < 8; c++) {
            const int j = (c < 4) ? ((tx << 2) + c) : (64 + (tx << 2) + (c - 4));
            float s = acc[r][c] + pe[j - i + (WSZ - 1)];
            if ((r >= 4) != (c >= 4)) s -= 1e9f;   // quadrant shift mask
            acc[r][c] = s;
            mx = fmaxf(mx, s);
        }
#pragma unroll
        for (int o = 8; o > 0; o >>= 1)
            mx = fmaxf(mx, __shfl_xor_sync(0xffffffffu, mx, o));
        float sum = 0.f;
#pragma unroll
        for (int c = 0; c < 8; c++) {
            float e = __expf(acc[r][c] - mx);
            acc[r][c] = e;
            sum += e;
        }
#pragma unroll
        for (int o = 8; o > 0; o >>= 1)
            sum += __shfl_xor_sync(0xffffffffu, sum, o);
        const float inv = 1.0f / sum;
#pragma unroll
        for (int c = 0; c < 8; c++) acc[r][c] *= inv;
    }

    __syncthreads();   // Qt/Kt reads complete before P overlay write
#pragma unroll
    for (int r = 0; r < 8; r++) {
        *(float4*)&Ps[rowi[r] * PADT + (tx << 2)] =
            make_float4(acc[r][0], acc[r][1], acc[r][2], acc[r][3]);
        *(float4*)&Ps[rowi[r] * PADT + 64 + (tx << 2)] =
            make_float4(acc[r][4], acc[r][5], acc[r][6], acc[r][7]);
    }
    __syncthreads();

    // out = P @ V   (out tile 128x64; micro 8 rows x 4 cols)
    float o[8][4];
#pragma unroll
    for (int r = 0; r < 8; r++)
#pragma unroll
        for (int c = 0; c < 4; c++) o[r][c] = 0.f;

#pragma unroll 4
    for (int j = 0; j < WSZ; j++) {
        float4 v = *(const float4*)&Vs[j * PADV + (tx << 2)];
#pragma unroll
        for (int r = 0; r < 8; r++) {
            float p = Ps[rowi[r] * PADT + j];
            o[r][0] = fmaf(p, v.x, o[r][0]);
            o[r][1] = fmaf(p, v.y, o[r][1]);
            o[r][2] = fmaf(p, v.z, o[r][2]);
            o[r][3] = fmaf(p, v.w, o[r][3]);
        }
    }

    // OUTPUT rearrange: token_out = pi*WSZ + w
#pragma unroll
    for (int r = 0; r < 8; r++) {
        const long orow = (long)((b << 12) + pi * WSZ + rowi[r]) * DMODEL
                        + h * DHD + (tx << 2);
        *(float4*)&g_att[orow] = make_float4(o[r][0], o[r][1], o[r][2], o[r][3]);
    }
}

// ---------------------------------------------------------------------------
extern "C" void kernel_launch(void* const* d_in, const int* in_sizes, int n_in,
                              void* d_out, int out_size)
{
    const float* x       = (const float*)d_in[0];
    const float* Wqkv    = (const float*)d_in[1];
    const float* pos_emb = (const float*)d_in[2];
    const float* Wout    = (const float*)d_in[3];
    const float* bout    = (const float*)d_in[4];
    float* out = (float*)d_out;

    cudaFuncSetAttribute(attn_kernel, cudaFuncAttributeMaxDynamicSharedMemorySize,
                         (int)(ATTN_SMEM_FLOATS * sizeof(float)));

    // 1) qkv = roll(x,-64) @ Wqkv   (3xTF32 tensor cores)
    gemm_tf32<0><<<dim3(12, 256), 256>>>(x, Wqkv, nullptr, nullptr);
    // 2) windowed attention (2048 windows)
    attn_kernel<<<2048, 256, ATTN_SMEM_FLOATS * sizeof(float)>>>(pos_emb);
    // 3) out = attn @ Wout + bout, rolled back by +64   (3xTF32)
    gemm_tf32<1><<<dim3(4, 256), 256>>>(nullptr, Wout, bout, out);
}

// round 4
// speedup vs baseline: 1.5233x; 1.2773x over previous
#include <cuda_runtime.h>
#include <cuda_bf16.h>

#define NTOK   4096
#define DMODEL 512
#define NH     8
#define DHD    64
#define WSZ    128
#define NP     32
#define DISP   64
#define QKV_LD 1536
#define MTOT   32768

// ---------------------------------------------------------------------------
// Scratch (device globals — allocation-free per harness rules)
// ---------------------------------------------------------------------------
__device__ float g_qkv[(size_t)MTOT * QKV_LD];            // gemm0 out (f32)
__device__ __nv_bfloat16 g_xhi[(size_t)MTOT * DMODEL];    // shifted x, hi plane
__device__ __nv_bfloat16 g_xlo[(size_t)MTOT * DMODEL];    // shifted x, lo plane
__device__ __nv_bfloat16 g_ahi[(size_t)MTOT * DMODEL];    // attn out, hi plane
__device__ __nv_bfloat16 g_alo[(size_t)MTOT * DMODEL];    // attn out, lo plane
__device__ __nv_bfloat16 g_wqkv_hi[(size_t)QKV_LD * DMODEL];  // W^T [n][k]
__device__ __nv_bfloat16 g_wqkv_lo[(size_t)QKV_LD * DMODEL];
__device__ __nv_bfloat16 g_wout_hi[(size_t)DMODEL * DMODEL];
__device__ __nv_bfloat16 g_wout_lo[(size_t)DMODEL * DMODEL];

// ---------------------------------------------------------------------------
// helpers
// ---------------------------------------------------------------------------
__device__ __forceinline__ unsigned smem_u32(const void* p) {
    return (unsigned)__cvta_generic_to_shared(p);
}
__device__ __forceinline__ unsigned pack2(__nv_bfloat16 a, __nv_bfloat16 b) {
    unsigned short ua = *(unsigned short*)&a, ub = *(unsigned short*)&b;
    return (unsigned)ua | ((unsigned)ub << 16);
}
__device__ __forceinline__ void mma_bf16(float* d, const unsigned* a, const unsigned* b) {
    asm volatile(
        "mma.sync.aligned.m16n8k16.row.col.f32.bf16.bf16.f32 "
        "{%0,%1,%2,%3}, {%4,%5,%6,%7}, {%8,%9}, {%0,%1,%2,%3};\n"
        : "+f"(d[0]), "+f"(d[1]), "+f"(d[2]), "+f"(d[3])
        : "r"(a[0]), "r"(a[1]), "r"(a[2]), "r"(a[3]), "r"(b[0]), "r"(b[1]));
}
#define CP16(dst, src) \
    asm volatile("cp.async.ca.shared.global [%0], [%1], 16;\n" :: "r"(dst), "l"(src))

// ---------------------------------------------------------------------------
// Prep 1: shifted x -> bf16 hi/lo planes.  out row m holds x row (n+DISP)%N.
// ---------------------------------------------------------------------------
__global__ void __launch_bounds__(128)
split_x_shift(const float* __restrict__ x)
{
    const int row = blockIdx.x;
    const int b = row >> 12, n = row & 4095;
    const float4* src = (const float4*)(x + (size_t)((b << 12) | ((n + DISP) & 4095)) * DMODEL);
    float4 v = src[threadIdx.x];
    __nv_bfloat16 h0 = __float2bfloat16(v.x), h1 = __float2bfloat16(v.y);
    __nv_bfloat16 h2 = __float2bfloat16(v.z), h3 = __float2bfloat16(v.w);
    __nv_bfloat16 l0 = __float2bfloat16(v.x - __bfloat162float(h0));
    __nv_bfloat16 l1 = __float2bfloat16(v.y - __bfloat162float(h1));
    __nv_bfloat16 l2 = __float2bfloat16(v.z - __bfloat162float(h2));
    __nv_bfloat16 l3 = __float2bfloat16(v.w - __bfloat162float(h3));
    const size_t o = (size_t)row * DMODEL + threadIdx.x * 4;
    *(uint2*)&g_xhi[o] = make_uint2(pack2(h0, h1), pack2(h2, h3));
    *(uint2*)&g_xlo[o] = make_uint2(pack2(l0, l1), pack2(l2, l3));
}

// ---------------------------------------------------------------------------
// Prep 2: W [K][N] -> W^T [N][K] bf16 hi/lo planes (smem-tiled transpose).
// WHICH 0: Wqkv (N=1536), WHICH 1: Wout (N=512). K=512.
// ---------------------------------------------------------------------------
template<int WHICH>
__global__ void __launch_bounds__(1024)
split_wT(const float* __restrict__ W)
{
    constexpr int K = DMODEL;
    constexpr int N = (WHICH == 0) ? QKV_LD : DMODEL;
    __nv_bfloat16* hi = (WHICH == 0) ? g_wqkv_hi : g_wout_hi;
    __nv_bfloat16* lo = (WHICH == 0) ? g_wqkv_lo : g_wout_lo;

    __shared__ float t[32][33];
    const int n0 = blockIdx.x << 5, k0 = blockIdx.y << 5;
    const int tx = threadIdx.x, ty = threadIdx.y;
    t[ty][tx] = W[(size_t)(k0 + ty) * N + n0 + tx];
    __syncthreads();
    const float v = t[tx][ty];   // = W[k0+tx][n0+ty]
    const size_t o = (size_t)(n0 + ty) * K + k0 + tx;
    __nv_bfloat16 h = __float2bfloat16(v);
    hi[o] = h;
    lo[o] = __float2bfloat16(v - __bfloat162float(h));
}

// ---------------------------------------------------------------------------
// 3-term bf16 tensor-core GEMM: C = Ahi@Bhi + Ahi@Blo + Alo@Bhi  (fp32 acc)
// 128x128x16 block tile, 256 thr, warp grid 2(M)x4(N), warp tile 64x32,
// m16n8k16 fragments as plain 32-bit LDS (A [m][k], B^T [n][k], pitch 24).
// MODE 0: A = g_x{hi,lo} (pre-shifted), B = Wqkv^T, C = g_qkv
// MODE 1: A = g_a{hi,lo}, B = Wout^T, C = out (+DISP roll scatter, +bias)
// ---------------------------------------------------------------------------
#define PITCH 24
#define NKIT  (DMODEL / 16)   // 32

template<int MODE>
__global__ void __launch_bounds__(256)
gemm_bf16(const float* __restrict__ bias, float* __restrict__ Cout)
{
    const __nv_bfloat16* __restrict__ Ahi = (MODE == 0) ? g_xhi : g_ahi;
    const __nv_bfloat16* __restrict__ Alo = (MODE == 0) ? g_xlo : g_alo;
    const __nv_bfloat16* __restrict__ Bhi = (MODE == 0) ? g_wqkv_hi : g_wout_hi;
    const __nv_bfloat16* __restrict__ Blo = (MODE == 0) ? g_wqkv_lo : g_wout_lo;
    float* __restrict__ C = (MODE == 0) ? (float*)g_qkv : Cout;
    constexpr int LDC = (MODE == 0) ? QKV_LD : DMODEL;

    __shared__ __align__(16) __nv_bfloat16 sAh[2][128 * PITCH];
    __shared__ __align__(16) __nv_bfloat16 sAl[2][128 * PITCH];
    __shared__ __align__(16) __nv_bfloat16 sBh[2][128 * PITCH];
    __shared__ __align__(16) __nv_bfloat16 sBl[2][128 * PITCH];

    const int tid  = threadIdx.x;
    const int lane = tid & 31;
    const int wid  = tid >> 5;
    const int g    = lane >> 2;       // 0..7
    const int c    = lane & 3;        // 0..3
    const int wm   = (wid >> 2) * 64; // 0 / 64
    const int wn   = (wid & 3) * 32;  // 0..96

    const int m0 = blockIdx.y << 7;
    const int n0 = blockIdx.x << 7;

    // cp.async assignments: thread -> (row = tid>>1, 16B half = tid&1)
    const int lr = tid >> 1;
    const int lh = (tid & 1) * 8;                 // bf16 elements
    const size_t agm = (size_t)(m0 + lr) * DMODEL + lh;
    const size_t bgm = (size_t)(n0 + lr) * DMODEL + lh;
    const unsigned sm_off = (unsigned)((lr * PITCH + lh) * sizeof(__nv_bfloat16));
    const unsigned dAh = smem_u32(sAh[0]) + sm_off;
    const unsigned dAl = smem_u32(sAl[0]) + sm_off;
    const unsigned dBh = smem_u32(sBh[0]) + sm_off;
    const unsigned dBl = smem_u32(sBl[0]) + sm_off;
    const unsigned stg = (unsigned)(128 * PITCH * sizeof(__nv_bfloat16));

    float acc[4][4][4];
#pragma unroll
    for (int mt = 0; mt < 4; mt++)
#pragma unroll
        for (int nt = 0; nt < 4; nt++)
#pragma unroll
            for (int i = 0; i < 4; i++) acc[mt][nt][i] = 0.f;

    // prefetch stage 0
    CP16(dAh, Ahi + agm); CP16(dAl, Alo + agm);
    CP16(dBh, Bhi + bgm); CP16(dBl, Blo + bgm);
    asm volatile("cp.async.commit_group;\n");

#pragma unroll 1
    for (int kt = 0; kt < NKIT; kt++) {
        const int s = kt & 1;
        if (kt + 1 < NKIT) {
            const unsigned s2 = (unsigned)((kt + 1) & 1) * stg;
            const size_t ka = agm + (kt + 1) * 16;
            const size_t kb = bgm + (kt + 1) * 16;
            CP16(dAh + s2, Ahi + ka); CP16(dAl + s2, Alo + ka);
            CP16(dBh + s2, Bhi + kb); CP16(dBl + s2, Blo + kb);
            asm volatile("cp.async.commit_group;\n");
            asm volatile("cp.async.wait_group 1;\n");
        } else {
            asm volatile("cp.async.wait_group 0;\n");
        }
        __syncthreads();

        const __nv_bfloat16* ah = sAh[s];
        const __nv_bfloat16* al = sAl[s];
        const __nv_bfloat16* bh = sBh[s];
        const __nv_bfloat16* bl = sBl[s];

        unsigned Bh[4][2], Bl[4][2];
#pragma unroll
        for (int nt = 0; nt < 4; nt++) {
            const int nb = (wn + nt * 8 + g) * PITCH + 2 * c;
            Bh[nt][0] = *(const unsigned*)&bh[nb];
            Bh[nt][1] = *(const unsigned*)&bh[nb + 8];
            Bl[nt][0] = *(const unsigned*)&bl[nb];
            Bl[nt][1] = *(const unsigned*)&bl[nb + 8];
        }
#pragma unroll
        for (int mt = 0; mt < 4; mt++) {
            const int r0 = (wm + mt * 16 + g) * PITCH + 2 * c;
            const int r8 = r0 + 8 * PITCH;
            unsigned Ah[4], Al[4];
            Ah[0] = *(const unsigned*)&ah[r0];     Ah[1] = *(const unsigned*)&ah[r8];
            Ah[2] = *(const unsigned*)&ah[r0 + 8]; Ah[3] = *(const unsigned*)&ah[r8 + 8];
            Al[0] = *(const unsigned*)&al[r0];     Al[1] = *(const unsigned*)&al[r8];
            Al[2] = *(const unsigned*)&al[r0 + 8]; Al[3] = *(const unsigned*)&al[r8 + 8];
#pragma unroll
            for (int nt = 0; nt < 4; nt++) {
                mma_bf16(acc[mt][nt], Al, Bh[nt]);
                mma_bf16(acc[mt][nt], Ah, Bl[nt]);
                mma_bf16(acc[mt][nt], Ah, Bh[nt]);
            }
        }
        __syncthreads();
    }

    // epilogue
    float2 bv[4];
    if (MODE == 1) {
#pragma unroll
        for (int nt = 0; nt < 4; nt++)
            bv[nt] = *(const float2*)&bias[n0 + wn + nt * 8 + 2 * c];
    }
#pragma unroll
    for (int mt = 0; mt < 4; mt++) {
#pragma unroll
        for (int half = 0; half < 2; half++) {
            const int row = m0 + wm + mt * 16 + g + half * 8;
            long crow;
            if (MODE == 1) {
                const int bb = row >> 12, nn = row & 4095;
                crow = (long)((bb << 12) | ((nn + DISP) & 4095)) * LDC;
            } else {
                crow = (long)row * LDC;
            }
#pragma unroll
            for (int nt = 0; nt < 4; nt++) {
                float x = acc[mt][nt][half * 2 + 0];
                float y = acc[mt][nt][half * 2 + 1];
                if (MODE == 1) { x += bv[nt].x; y += bv[nt].y; }
                *(float2*)&C[crow + n0 + wn + nt * 8 + 2 * c] = make_float2(x, y);
            }
        }
    }
}

// ---------------------------------------------------------------------------
// Windowed attention (unchanged math); writes bf16 hi/lo planes for gemm1.
// Input tokens of window pi:  n_in  = w*NP + pi
// Output token of (pi, w):    n_out = pi*WSZ + w
// ---------------------------------------------------------------------------
#define PADT 132
#define PADV 68
#define ATTN_SMEM_FLOATS (2 * 64 * PADT + 128 * PADV)   // 100 KB

__global__ void __launch_bounds__(256)
attn_kernel(const float* __restrict__ pos_emb)
{
    extern __shared__ float sm[];
    float* Qt = sm;                 // [64][132]
    float* Kt = sm + 64 * PADT;     // [64][132]
    float* Vs = sm + 2 * 64 * PADT; // [128][68]
    float* Ps = sm;                 // [128][132] overlays Qt+Kt

    __shared__ float pe[2 * WSZ - 1];

    const int tid = threadIdx.x;
    const int ty = tid >> 4, tx = tid & 15;
    const int blk = blockIdx.x;
    const int pi = blk & 31;
    const int h  = (blk >> 5) & 7;
    const int b  = blk >> 8;

    for (int i = tid; i < 2 * WSZ - 1; i += 256) pe[i] = pos_emb[i];

    {
        const int w    = tid >> 1;
        const int half = tid & 1;
        const long rbase = (long)((b << 12) + w * NP + pi) * QKV_LD + h * DHD;
#pragma unroll
        for (int j = 0; j < 8; j++) {
            const int d = (half << 5) + (j << 2);
            float4 q = *(const float4*)&g_qkv[rbase + d];
            float4 k = *(const float4*)&g_qkv[rbase + 512 + d];
            float4 v = *(const float4*)&g_qkv[rbase + 1024 + d];
            Qt[(d + 0) * PADT + w] = q.x * 0.125f;
            Qt[(d + 1) * PADT + w] = q.y * 0.125f;
            Qt[(d + 2) * PADT + w] = q.z * 0.125f;
            Qt[(d + 3) * PADT + w] = q.w * 0.125f;
            Kt[(d + 0) * PADT + w] = k.x;
            Kt[(d + 1) * PADT + w] = k.y;
            Kt[(d + 2) * PADT + w] = k.z;
            Kt[(d + 3) * PADT + w] = k.w;
            *(float4*)&Vs[w * PADV + d] = v;
        }
    }
    __syncthreads();

    int rowi[8];
#pragma unroll
    for (int r = 0; r < 8; r++)
        rowi[r] = (r < 4) ? ((ty << 2) + r) : (64 + (ty << 2) + (r - 4));

    float acc[8][8];
#pragma unroll
    for (int r = 0; r < 8; r++)
#pragma unroll
        for (int c = 0; c < 8; c++) acc[r][c] = 0.f;

#pragma unroll 8
    for (int d = 0; d < 64; d++) {
        float4 a0 = *(const float4*)&Qt[d * PADT + (ty << 2)];
        float4 a1 = *(const float4*)&Qt[d * PADT + 64 + (ty << 2)];
        float4 b0 = *(const float4*)&Kt[d * PADT + (tx << 2)];
        float4 b1 = *(const float4*)&Kt[d * PADT + 64 + (tx << 2)];
        float qr[8] = {a0.x, a0.y, a0.z, a0.w, a1.x, a1.y, a1.z, a1.w};
        float kr[8] = {b0.x, b0.y, b0.z, b0.w, b1.x, b1.y, b1.z, b1.w};
#pragma unroll
        for (int r = 0; r < 8; r++)
#pragma unroll
            for (int c = 0; c < 8; c++)
                acc[r][c] = fmaf(qr[r], kr[c], acc[r][c]);
    }

#pragma unroll
    for (int r = 0; r < 8; r++) {
        const int i = rowi[r];
        float mx = -3.0e38f;
#pragma unroll
        for (int c = 0; c < 8; c++) {
            const int j = (c < 4) ? ((tx << 2) + c) : (64 + (tx << 2) + (c - 4));
            float s = acc[r][c] + pe[j - i + (WSZ - 1)];
            if ((r >= 4) != (c >= 4)) s -= 1e9f;
            acc[r][c] = s;
            mx = fmaxf(mx, s);
        }
#pragma unroll
        for (int o = 8; o > 0; o >>= 1)
            mx = fmaxf(mx, __shfl_xor_sync(0xffffffffu, mx, o));
        float sum = 0.f;
#pragma unroll
        for (int c = 0; c < 8; c++) {
            float e = __expf(acc[r][c] - mx);
            acc[r][c] = e;
            sum += e;
        }
#pragma unroll
        for (int o = 8; o > 0; o >>= 1)
            sum += __shfl_xor_sync(0xffffffffu, sum, o);
        const float inv = 1.0f / sum;
#pragma unroll
        for (int c = 0; c < 8; c++) acc[r][c] *= inv;
    }

    __syncthreads();
#pragma unroll
    for (int r = 0; r < 8; r++) {
        *(float4*)&Ps[rowi[r] * PADT + (tx << 2)] =
            make_float4(acc[r][0], acc[r][1], acc[r][2], acc[r][3]);
        *(float4*)&Ps[rowi[r] * PADT + 64 + (tx << 2)] =
            make_float4(acc[r][4], acc[r][5], acc[r][6], acc[r][7]);
    }
    __syncthreads();

    float o[8][4];
#pragma unroll
    for (int r = 0; r < 8; r++)
#pragma unroll
        for (int c = 0; c < 4; c++) o[r][c] = 0.f;

#pragma unroll 4
    for (int j = 0; j < WSZ; j++) {
        float4 v = *(const float4*)&Vs[j * PADV + (tx << 2)];
#pragma unroll
        for (int r = 0; r < 8; r++) {
            float p = Ps[rowi[r] * PADT + j];
            o[r][0] = fmaf(p, v.x, o[r][0]);
            o[r][1] = fmaf(p, v.y, o[r][1]);
            o[r][2] = fmaf(p, v.z, o[r][2]);
            o[r][3] = fmaf(p, v.w, o[r][3]);
        }
    }

    // write bf16 hi/lo planes; token_out = pi*WSZ + w
#pragma unroll
    for (int r = 0; r < 8; r++) {
        const size_t orow = ((size_t)(b << 12) + pi * WSZ + rowi[r]) * DMODEL
                          + h * DHD + (tx << 2);
        __nv_bfloat16 h0 = __float2bfloat16(o[r][0]);
        __nv_bfloat16 h1 = __float2bfloat16(o[r][1]);
        __nv_bfloat16 h2 = __float2bfloat16(o[r][2]);
        __nv_bfloat16 h3 = __float2bfloat16(o[r][3]);
        __nv_bfloat16 l0 = __float2bfloat16(o[r][0] - __bfloat162float(h0));
        __nv_bfloat16 l1 = __float2bfloat16(o[r][1] - __bfloat162float(h1));
        __nv_bfloat16 l2 = __float2bfloat16(o[r][2] - __bfloat162float(h2));
        __nv_bfloat16 l3 = __float2bfloat16(o[r][3] - __bfloat162float(h3));
        *(uint2*)&g_ahi[orow] = make_uint2(pack2(h0, h1), pack2(h2, h3));
        *(uint2*)&g_alo[orow] = make_uint2(pack2(l0, l1), pack2(l2, l3));
    }
}

// ---------------------------------------------------------------------------
extern "C" void kernel_launch(void* const* d_in, const int* in_sizes, int n_in,
                              void* d_out, int out_size)
{
    const float* x       = (const float*)d_in[0];
    const float* Wqkv    = (const float*)d_in[1];
    const float* pos_emb = (const float*)d_in[2];
    const float* Wout    = (const float*)d_in[3];
    const float* bout    = (const float*)d_in[4];
    float* out = (float*)d_out;

    cudaFuncSetAttribute(attn_kernel, cudaFuncAttributeMaxDynamicSharedMemorySize,
                         (int)(ATTN_SMEM_FLOATS * sizeof(float)));

    // prep: bf16 hi/lo planes (shifted x; transposed weights)
    split_x_shift<<<MTOT, 128>>>(x);
    split_wT<0><<<dim3(QKV_LD / 32, DMODEL / 32), dim3(32, 32)>>>(Wqkv);
    split_wT<1><<<dim3(DMODEL / 32, DMODEL / 32), dim3(32, 32)>>>(Wout);

    // 1) qkv = roll(x,-64) @ Wqkv   (3-term bf16 tensor cores)
    gemm_bf16<0><<<dim3(12, 256), 256>>>(nullptr, nullptr);
    // 2) windowed attention (2048 windows)
    attn_kernel<<<2048, 256, ATTN_SMEM_FLOATS * sizeof(float)>>>(pos_emb);
    // 3) out = attn @ Wout + bout, rolled back by +64
    gemm_bf16<1><<<dim3(4, 256), 256>>>(bout, out);
}

// round 5
// speedup vs baseline: 2.0092x; 1.3190x over previous
#include <cuda_runtime.h>
#include <cuda_bf16.h>

#define NTOK   4096
#define DMODEL 512
#define NH     8
#define DHD    64
#define WSZ    128
#define NP     32
#define DISP   64
#define QKV_LD 1536
#define MTOT   32768

// ---------------------------------------------------------------------------
// Scratch (device globals — allocation-free per harness rules)
// ---------------------------------------------------------------------------
__device__ float g_qkv[(size_t)MTOT * QKV_LD];            // gemm0 out (f32)
__device__ __nv_bfloat16 g_xhi[(size_t)MTOT * DMODEL];    // shifted x, hi plane
__device__ __nv_bfloat16 g_xlo[(size_t)MTOT * DMODEL];    // shifted x, lo plane
__device__ __nv_bfloat16 g_ahi[(size_t)MTOT * DMODEL];    // attn out, hi plane
__device__ __nv_bfloat16 g_alo[(size_t)MTOT * DMODEL];    // attn out, lo plane
__device__ __nv_bfloat16 g_wqkv_hi[(size_t)QKV_LD * DMODEL];  // W^T [n][k]
__device__ __nv_bfloat16 g_wqkv_lo[(size_t)QKV_LD * DMODEL];
__device__ __nv_bfloat16 g_wout_hi[(size_t)DMODEL * DMODEL];
__device__ __nv_bfloat16 g_wout_lo[(size_t)DMODEL * DMODEL];

// ---------------------------------------------------------------------------
// helpers
// ---------------------------------------------------------------------------
__device__ __forceinline__ unsigned smem_u32(const void* p) {
    return (unsigned)__cvta_generic_to_shared(p);
}
__device__ __forceinline__ unsigned pack2(__nv_bfloat16 a, __nv_bfloat16 b) {
    unsigned short ua = *(unsigned short*)&a, ub = *(unsigned short*)&b;
    return (unsigned)ua | ((unsigned)ub << 16);
}
__device__ __forceinline__ unsigned packf2(float a, float b) {   // low=a, high=b, rn
    __nv_bfloat162 v = __float22bfloat162_rn(make_float2(a, b));
    return *(unsigned*)&v;
}
__device__ __forceinline__ void mma_bf16(float* d, const unsigned* a, const unsigned* b) {
    asm volatile(
        "mma.sync.aligned.m16n8k16.row.col.f32.bf16.bf16.f32 "
        "{%0,%1,%2,%3}, {%4,%5,%6,%7}, {%8,%9}, {%0,%1,%2,%3};\n"
        : "+f"(d[0]), "+f"(d[1]), "+f"(d[2]), "+f"(d[3])
        : "r"(a[0]), "r"(a[1]), "r"(a[2]), "r"(a[3]), "r"(b[0]), "r"(b[1]));
}
__device__ __forceinline__ void ldsm4(unsigned* r, unsigned a) {
    asm volatile("ldmatrix.sync.aligned.m8n8.x4.shared.b16 {%0,%1,%2,%3}, [%4];"
        : "=r"(r[0]), "=r"(r[1]), "=r"(r[2]), "=r"(r[3]) : "r"(a));
}
__device__ __forceinline__ void ldsm4t(unsigned* r, unsigned a) {
    asm volatile("ldmatrix.sync.aligned.m8n8.x4.trans.shared.b16 {%0,%1,%2,%3}, [%4];"
        : "=r"(r[0]), "=r"(r[1]), "=r"(r[2]), "=r"(r[3]) : "r"(a));
}
#define CP16(dst, src) \
    asm volatile("cp.async.ca.shared.global [%0], [%1], 16;\n" :: "r"(dst), "l"(src))

// ---------------------------------------------------------------------------
// Prep 1: shifted x -> bf16 hi/lo planes.
// ---------------------------------------------------------------------------
__global__ void __launch_bounds__(128)
split_x_shift(const float* __restrict__ x)
{
    const int row = blockIdx.x;
    const int b = row >> 12, n = row & 4095;
    const float4* src = (const float4*)(x + (size_t)((b << 12) | ((n + DISP) & 4095)) * DMODEL);
    float4 v = src[threadIdx.x];
    __nv_bfloat16 h0 = __float2bfloat16(v.x), h1 = __float2bfloat16(v.y);
    __nv_bfloat16 h2 = __float2bfloat16(v.z), h3 = __float2bfloat16(v.w);
    __nv_bfloat16 l0 = __float2bfloat16(v.x - __bfloat162float(h0));
    __nv_bfloat16 l1 = __float2bfloat16(v.y - __bfloat162float(h1));
    __nv_bfloat16 l2 = __float2bfloat16(v.z - __bfloat162float(h2));
    __nv_bfloat16 l3 = __float2bfloat16(v.w - __bfloat162float(h3));
    const size_t o = (size_t)row * DMODEL + threadIdx.x * 4;
    *(uint2*)&g_xhi[o] = make_uint2(pack2(h0, h1), pack2(h2, h3));
    *(uint2*)&g_xlo[o] = make_uint2(pack2(l0, l1), pack2(l2, l3));
}

// ---------------------------------------------------------------------------
// Prep 2: W [K][N] -> W^T [N][K] bf16 hi/lo planes.
// ---------------------------------------------------------------------------
template<int WHICH>
__global__ void __launch_bounds__(1024)
split_wT(const float* __restrict__ W)
{
    constexpr int K = DMODEL;
    constexpr int N = (WHICH == 0) ? QKV_LD : DMODEL;
    __nv_bfloat16* hi = (WHICH == 0) ? g_wqkv_hi : g_wout_hi;
    __nv_bfloat16* lo = (WHICH == 0) ? g_wqkv_lo : g_wout_lo;

    __shared__ float t[32][33];
    const int n0 = blockIdx.x << 5, k0 = blockIdx.y << 5;
    const int tx = threadIdx.x, ty = threadIdx.y;
    t[ty][tx] = W[(size_t)(k0 + ty) * N + n0 + tx];
    __syncthreads();
    const float v = t[tx][ty];
    const size_t o = (size_t)(n0 + ty) * K + k0 + tx;
    __nv_bfloat16 h = __float2bfloat16(v);
    hi[o] = h;
    lo[o] = __float2bfloat16(v - __bfloat162float(h));
}

// ---------------------------------------------------------------------------
// 3-term bf16 GEMM with ldmatrix fragments.
// 128x128x16 tile, 256 thr, warps 2(M)x4(N), warp tile 64x32.
// ---------------------------------------------------------------------------
#define PITCH 24
#define NKIT  (DMODEL / 16)

template<int MODE>
__global__ void __launch_bounds__(256)
gemm_bf16(const float* __restrict__ bias, float* __restrict__ Cout)
{
    const __nv_bfloat16* __restrict__ Ahi = (MODE == 0) ? g_xhi : g_ahi;
    const __nv_bfloat16* __restrict__ Alo = (MODE == 0) ? g_xlo : g_alo;
    const __nv_bfloat16* __restrict__ Bhi = (MODE == 0) ? g_wqkv_hi : g_wout_hi;
    const __nv_bfloat16* __restrict__ Blo = (MODE == 0) ? g_wqkv_lo : g_wout_lo;
    float* __restrict__ C = (MODE == 0) ? (float*)g_qkv : Cout;
    constexpr int LDC = (MODE == 0) ? QKV_LD : DMODEL;

    __shared__ __align__(16) __nv_bfloat16 sAh[2][128 * PITCH];
    __shared__ __align__(16) __nv_bfloat16 sAl[2][128 * PITCH];
    __shared__ __align__(16) __nv_bfloat16 sBh[2][128 * PITCH];
    __shared__ __align__(16) __nv_bfloat16 sBl[2][128 * PITCH];

    const int tid  = threadIdx.x;
    const int lane = tid & 31;
    const int wid  = tid >> 5;
    const int g    = lane >> 2;
    const int c    = lane & 3;
    const int wm   = (wid >> 2) * 64;
    const int wn   = (wid & 3) * 32;

    const int m0 = blockIdx.y << 7;
    const int n0 = blockIdx.x << 7;

    const int lr = tid >> 1;
    const int lh = (tid & 1) * 8;
    const size_t agm = (size_t)(m0 + lr) * DMODEL + lh;
    const size_t bgm = (size_t)(n0 + lr) * DMODEL + lh;
    const unsigned sm_off = (unsigned)((lr * PITCH + lh) * sizeof(__nv_bfloat16));
    const unsigned dAh = smem_u32(sAh[0]) + sm_off;
    const unsigned dAl = smem_u32(sAl[0]) + sm_off;
    const unsigned dBh = smem_u32(sBh[0]) + sm_off;
    const unsigned dBl = smem_u32(sBl[0]) + sm_off;
    const unsigned stg = (unsigned)(128 * PITCH * sizeof(__nv_bfloat16));

    // ldmatrix lane offsets (bytes)
    const unsigned aoff = (unsigned)((wm + (lane & 15)) * (PITCH * 2) + (lane & 16));
    const unsigned boff = (unsigned)((wn + (lane & 7) + ((lane & 16) >> 1)) * (PITCH * 2)
                                     + ((lane & 8) << 1));
    const unsigned lAh = smem_u32(sAh[0]) + aoff;
    const unsigned lAl = smem_u32(sAl[0]) + aoff;
    const unsigned lBh = smem_u32(sBh[0]) + boff;
    const unsigned lBl = smem_u32(sBl[0]) + boff;

    float acc[4][4][4];
#pragma unroll
    for (int mt = 0; mt < 4; mt++)
#pragma unroll
        for (int nt = 0; nt < 4; nt++)
#pragma unroll
            for (int i = 0; i < 4; i++) acc[mt][nt][i] = 0.f;

    CP16(dAh, Ahi + agm); CP16(dAl, Alo + agm);
    CP16(dBh, Bhi + bgm); CP16(dBl, Blo + bgm);
    asm volatile("cp.async.commit_group;\n");

#pragma unroll 1
    for (int kt = 0; kt < NKIT; kt++) {
        const unsigned sb = (unsigned)(kt & 1) * stg;
        if (kt + 1 < NKIT) {
            const unsigned s2 = (unsigned)((kt + 1) & 1) * stg;
            const size_t ka = agm + (kt + 1) * 16;
            const size_t kb = bgm + (kt + 1) * 16;
            CP16(dAh + s2, Ahi + ka); CP16(dAl + s2, Alo + ka);
            CP16(dBh + s2, Bhi + kb); CP16(dBl + s2, Blo + kb);
            asm volatile("cp.async.commit_group;\n");
            asm volatile("cp.async.wait_group 1;\n");
        } else {
            asm volatile("cp.async.wait_group 0;\n");
        }
        __syncthreads();

        unsigned Ah[4][4], Al[4][4];
#pragma unroll
        for (int mt = 0; mt < 4; mt++) {
            ldsm4(Ah[mt], lAh + sb + mt * 16 * (PITCH * 2));
            ldsm4(Al[mt], lAl + sb + mt * 16 * (PITCH * 2));
        }
        unsigned Bh[2][4], Bl[2][4];
#pragma unroll
        for (int p = 0; p < 2; p++) {
            ldsm4(Bh[p], lBh + sb + p * 16 * (PITCH * 2));
            ldsm4(Bl[p], lBl + sb + p * 16 * (PITCH * 2));
        }
#pragma unroll
        for (int mt = 0; mt < 4; mt++)
#pragma unroll
            for (int nt = 0; nt < 4; nt++) {
                const unsigned* bh = &Bh[nt >> 1][(nt & 1) * 2];
                const unsigned* bl = &Bl[nt >> 1][(nt & 1) * 2];
                mma_bf16(acc[mt][nt], Al[mt], bh);
                mma_bf16(acc[mt][nt], Ah[mt], bl);
                mma_bf16(acc[mt][nt], Ah[mt], bh);
            }
        __syncthreads();
    }

    float2 bv[4];
    if (MODE == 1) {
#pragma unroll
        for (int nt = 0; nt < 4; nt++)
            bv[nt] = *(const float2*)&bias[n0 + wn + nt * 8 + 2 * c];
    }
#pragma unroll
    for (int mt = 0; mt < 4; mt++) {
#pragma unroll
        for (int half = 0; half < 2; half++) {
            const int row = m0 + wm + mt * 16 + g + half * 8;
            long crow;
            if (MODE == 1) {
                const int bb = row >> 12, nn = row & 4095;
                crow = (long)((bb << 12) | ((nn + DISP) & 4095)) * LDC;
            } else {
                crow = (long)row * LDC;
            }
#pragma unroll
            for (int nt = 0; nt < 4; nt++) {
                float x = acc[mt][nt][half * 2 + 0];
                float y = acc[mt][nt][half * 2 + 1];
                if (MODE == 1) { x += bv[nt].x; y += bv[nt].y; }
                *(float2*)&C[crow + n0 + wn + nt * 8 + 2 * c] = make_float2(x, y);
            }
        }
    }
}

// ---------------------------------------------------------------------------
// Tensor-core windowed attention. One block per (b,h,window), 8 warps.
// Warp w owns rows w*16..w*16+15. S: 3-term bf16 MMA (16 nt tiles of n=8).
// Softmax in fragments; P repacked in regs; PV: 3-term bf16 MMA.
// SMEM: Q,K,V hi/lo planes [128][72] bf16 (pitch 144B, conflict-free LDSM).
// ---------------------------------------------------------------------------
#define APIT 72          // bf16 elements per row
#define APITB (APIT * 2) // bytes
#define PLANE_B (128 * APITB)   // 18432 bytes
#define ATTN_SMEM_B (6 * PLANE_B)

__global__ void __launch_bounds__(256)
attn_kernel(const float* __restrict__ pos_emb)
{
    extern __shared__ __align__(16) char smc[];
    __nv_bfloat16* Qh = (__nv_bfloat16*)(smc + 0 * PLANE_B);
    __nv_bfloat16* Ql = (__nv_bfloat16*)(smc + 1 * PLANE_B);
    __nv_bfloat16* Kh = (__nv_bfloat16*)(smc + 2 * PLANE_B);
    __nv_bfloat16* Kl = (__nv_bfloat16*)(smc + 3 * PLANE_B);
    __nv_bfloat16* Vh = (__nv_bfloat16*)(smc + 4 * PLANE_B);
    __nv_bfloat16* Vl = (__nv_bfloat16*)(smc + 5 * PLANE_B);
    __shared__ float pe[2 * WSZ - 1];

    const int tid  = threadIdx.x;
    const int lane = tid & 31;
    const int w    = tid >> 5;
    const int g    = lane >> 2;
    const int c    = lane & 3;
    const int blk  = blockIdx.x;
    const int pi   = blk & 31;
    const int h    = (blk >> 5) & 7;
    const int b    = blk >> 8;

    for (int i = tid; i < 2 * WSZ - 1; i += 256) pe[i] = pos_emb[i];

    {   // load Q (scaled), K, V; split to hi/lo planes
        const int tok = tid >> 1;
        const int d0  = (tid & 1) * 32;
        const size_t rbase = ((size_t)(b << 12) + tok * NP + pi) * QKV_LD + h * DHD;
        const int so = tok * APIT;
#pragma unroll
        for (int j = 0; j < 8; j += 2) {   // 2 float4 per iter per tensor
#pragma unroll
            for (int u = 0; u < 2; u++) {
                const int d = d0 + (j + u) * 4;
                float4 q = *(const float4*)&g_qkv[rbase + d];
                float4 k = *(const float4*)&g_qkv[rbase + 512 + d];
                float4 v = *(const float4*)&g_qkv[rbase + 1024 + d];
                q.x *= 0.125f; q.y *= 0.125f; q.z *= 0.125f; q.w *= 0.125f;
                // Q
                unsigned qh01 = packf2(q.x, q.y), qh23 = packf2(q.z, q.w);
                float qr0 = __uint_as_float(qh01 << 16), qr1 = __uint_as_float(qh01 & 0xffff0000u);
                float qr2 = __uint_as_float(qh23 << 16), qr3 = __uint_as_float(qh23 & 0xffff0000u);
                *(uint2*)&Qh[so + d] = make_uint2(qh01, qh23);
                *(uint2*)&Ql[so + d] = make_uint2(packf2(q.x - qr0, q.y - qr1),
                                                  packf2(q.z - qr2, q.w - qr3));
                // K
                unsigned kh01 = packf2(k.x, k.y), kh23 = packf2(k.z, k.w);
                float kr0 = __uint_as_float(kh01 << 16), kr1 = __uint_as_float(kh01 & 0xffff0000u);
                float kr2 = __uint_as_float(kh23 << 16), kr3 = __uint_as_float(kh23 & 0xffff0000u);
                *(uint2*)&Kh[so + d] = make_uint2(kh01, kh23);
                *(uint2*)&Kl[so + d] = make_uint2(packf2(k.x - kr0, k.y - kr1),
                                                  packf2(k.z - kr2, k.w - kr3));
                // V
                unsigned vh01 = packf2(v.x, v.y), vh23 = packf2(v.z, v.w);
                float vr0 = __uint_as_float(vh01 << 16), vr1 = __uint_as_float(vh01 & 0xffff0000u);
                float vr2 = __uint_as_float(vh23 << 16), vr3 = __uint_as_float(vh23 & 0xffff0000u);
                *(uint2*)&Vh[so + d] = make_uint2(vh01, vh23);
                *(uint2*)&Vl[so + d] = make_uint2(packf2(v.x - vr0, v.y - vr1),
                                                  packf2(v.z - vr2, v.w - vr3));
            }
        }
    }
    __syncthreads();

    // ---- S = (Q*scale) @ K^T : 3-term bf16, acc 16 nt tiles ----
    float accS[16][4];
#pragma unroll
    for (int nt = 0; nt < 16; nt++)
#pragma unroll
        for (int i = 0; i < 4; i++) accS[nt][i] = 0.f;

    const unsigned qoff = (unsigned)((w * 16 + (lane & 15)) * APITB + (lane & 16));
    const unsigned koff = (unsigned)(((lane & 7) + ((lane & 16) >> 1)) * APITB
                                     + ((lane & 8) << 1));
    const unsigned uQh = smem_u32(Qh) + qoff, uQl = smem_u32(Ql) + qoff;
    const unsigned uKh = smem_u32(Kh) + koff, uKl = smem_u32(Kl) + koff;

#pragma unroll
    for (int kc = 0; kc < 4; kc++) {
        unsigned qh[4], ql[4];
        ldsm4(qh, uQh + kc * 32);
        ldsm4(ql, uQl + kc * 32);
#pragma unroll
        for (int p = 0; p < 8; p++) {
            unsigned kh[4], kl[4];
            ldsm4(kh, uKh + p * 16 * APITB + kc * 32);
            ldsm4(kl, uKl + p * 16 * APITB + kc * 32);
            mma_bf16(accS[2 * p + 0], ql, kh + 0);
            mma_bf16(accS[2 * p + 0], qh, kl + 0);
            mma_bf16(accS[2 * p + 0], qh, kh + 0);
            mma_bf16(accS[2 * p + 1], ql, kh + 2);
            mma_bf16(accS[2 * p + 1], qh, kl + 2);
            mma_bf16(accS[2 * p + 1], qh, kh + 2);
        }
    }

    // ---- bias + shift mask + softmax on fragments ----
    const int i0 = w * 16 + g;
    const int i1 = i0 + 8;
    const bool q0 = (i0 >= 64), q1 = (i1 >= 64);
    float mx0 = -3.0e38f, mx1 = -3.0e38f;
#pragma unroll
    for (int nt = 0; nt < 16; nt++) {
#pragma unroll
        for (int e = 0; e < 2; e++) {
            const int j = nt * 8 + 2 * c + e;
            const bool jq = (j >= 64);
            float s0 = accS[nt][e]     + pe[j - i0 + (WSZ - 1)];
            float s1 = accS[nt][2 + e] + pe[j - i1 + (WSZ - 1)];
            if (q0 != jq) s0 -= 1e9f;
            if (q1 != jq) s1 -= 1e9f;
            accS[nt][e] = s0;     mx0 = fmaxf(mx0, s0);
            accS[nt][2 + e] = s1; mx1 = fmaxf(mx1, s1);
        }
    }
    mx0 = fmaxf(mx0, __shfl_xor_sync(0xffffffffu, mx0, 1));
    mx0 = fmaxf(mx0, __shfl_xor_sync(0xffffffffu, mx0, 2));
    mx1 = fmaxf(mx1, __shfl_xor_sync(0xffffffffu, mx1, 1));
    mx1 = fmaxf(mx1, __shfl_xor_sync(0xffffffffu, mx1, 2));
    float sm0 = 0.f, sm1 = 0.f;
#pragma unroll
    for (int nt = 0; nt < 16; nt++) {
#pragma unroll
        for (int e = 0; e < 2; e++) {
            float e0 = __expf(accS[nt][e] - mx0);
            float e1 = __expf(accS[nt][2 + e] - mx1);
            accS[nt][e] = e0;     sm0 += e0;
            accS[nt][2 + e] = e1; sm1 += e1;
        }
    }
    sm0 += __shfl_xor_sync(0xffffffffu, sm0, 1);
    sm0 += __shfl_xor_sync(0xffffffffu, sm0, 2);
    sm1 += __shfl_xor_sync(0xffffffffu, sm1, 1);
    sm1 += __shfl_xor_sync(0xffffffffu, sm1, 2);
    const float inv0 = 1.0f / sm0, inv1 = 1.0f / sm1;
#pragma unroll
    for (int nt = 0; nt < 16; nt++) {
        accS[nt][0] *= inv0; accS[nt][1] *= inv0;
        accS[nt][2] *= inv1; accS[nt][3] *= inv1;
    }

    // ---- out = P @ V : 3-term bf16, P from registers ----
    float out[8][4];
#pragma unroll
    for (int nt = 0; nt < 8; nt++)
#pragma unroll
        for (int i = 0; i < 4; i++) out[nt][i] = 0.f;

    const unsigned voff = (unsigned)((lane & 15) * APITB + (lane & 16));
    const unsigned uVh = smem_u32(Vh) + voff, uVl = smem_u32(Vl) + voff;

#pragma unroll
    for (int kc = 0; kc < 8; kc++) {
        unsigned a_hi[4], a_lo[4];
#pragma unroll
        for (int q = 0; q < 4; q++) {   // q: {nt=2kc,row0},{2kc,row1},{2kc+1,row0},{2kc+1,row1}
            const int nt = 2 * kc + (q >> 1);
            const int e0 = (q & 1) * 2;
            const float v0 = accS[nt][e0], v1 = accS[nt][e0 + 1];
            const unsigned hh = packf2(v0, v1);
            a_hi[q] = hh;
            const float r0 = __uint_as_float(hh << 16);
            const float r1 = __uint_as_float(hh & 0xffff0000u);
            a_lo[q] = packf2(v0 - r0, v1 - r1);
        }
        // a-order must be {row g k0-7, row g+8 k0-7, row g k8-15, row g+8 k8-15}
        // q mapping gives {nt,row0},{nt,row1},{nt+1,row0},{nt+1,row1} = exactly that.
#pragma unroll
        for (int p = 0; p < 4; p++) {
            unsigned vh[4], vl[4];
            ldsm4t(vh, uVh + kc * 16 * APITB + p * 32);
            ldsm4t(vl, uVl + kc * 16 * APITB + p * 32);
            mma_bf16(out[2 * p + 0], a_hi, vh + 0);
            mma_bf16(out[2 * p + 0], a_hi, vl + 0);
            mma_bf16(out[2 * p + 0], a_lo, vh + 0);
            mma_bf16(out[2 * p + 1], a_hi, vh + 2);
            mma_bf16(out[2 * p + 1], a_hi, vl + 2);
            mma_bf16(out[2 * p + 1], a_lo, vh + 2);
        }
    }

    // ---- epilogue: split to bf16 hi/lo planes; token_out = pi*WSZ + row ----
    const size_t rb0 = ((size_t)(b << 12) + pi * WSZ + i0) * DMODEL + h * DHD + 2 * c;
    const size_t rb1 = ((size_t)(b << 12) + pi * WSZ + i1) * DMODEL + h * DHD + 2 * c;
#pragma unroll
    for (int p = 0; p < 8; p++) {
        const float v0 = out[p][0], v1 = out[p][1];
        unsigned hh = packf2(v0, v1);
        float r0 = __uint_as_float(hh << 16), r1 = __uint_as_float(hh & 0xffff0000u);
        *(unsigned*)&g_ahi[rb0 + p * 8] = hh;
        *(unsigned*)&g_alo[rb0 + p * 8] = packf2(v0 - r0, v1 - r1);
        const float u0 = out[p][2], u1 = out[p][3];
        unsigned hh1 = packf2(u0, u1);
        float s0 = __uint_as_float(hh1 << 16), s1 = __uint_as_float(hh1 & 0xffff0000u);
        *(unsigned*)&g_ahi[rb1 + p * 8] = hh1;
        *(unsigned*)&g_alo[rb1 + p * 8] = packf2(u0 - s0, u1 - s1);
    }
}

// ---------------------------------------------------------------------------
extern "C" void kernel_launch(void* const* d_in, const int* in_sizes, int n_in,
                              void* d_out, int out_size)
{
    const float* x       = (const float*)d_in[0];
    const float* Wqkv    = (const float*)d_in[1];
    const float* pos_emb = (const float*)d_in[2];
    const float* Wout    = (const float*)d_in[3];
    const float* bout    = (const float*)d_in[4];
    float* out = (float*)d_out;

    cudaFuncSetAttribute(attn_kernel, cudaFuncAttributeMaxDynamicSharedMemorySize,
                         ATTN_SMEM_B);

    split_x_shift<<<MTOT, 128>>>(x);
    split_wT<0><<<dim3(QKV_LD / 32, DMODEL / 32), dim3(32, 32)>>>(Wqkv);
    split_wT<1><<<dim3(DMODEL / 32, DMODEL / 32), dim3(32, 32)>>>(Wout);

    gemm_bf16<0><<<dim3(12, 256), 256>>>(nullptr, nullptr);
    attn_kernel<<<2048, 256, ATTN_SMEM_B>>>(pos_emb);
    gemm_bf16<1><<<dim3(4, 256), 256>>>(bout, out);
}